// round 5
// baseline (speedup 1.0000x reference)
#include <cuda_runtime.h>

// Problem constants (from reference_code)
#define Hn    50000
#define INn   50000
#define NNZn  800000
#define Bn    8
#define Tn    32

#define NB        ((Hn + 255) / 256)   // 196 scan blocks per matrix
#define MAXWARPS  16384
#define SPAIRS    2048                 // smem pair capacity per block

// ---------------- device scratch (static globals; no runtime allocation) ----
__device__ float g_xT[(size_t)Tn * INn * Bn];      // x transposed -> (T, IN, B)
__device__ float g_ihpre[(size_t)Tn * Hn * Bn];    // ih spmm + bias, (T, H, B)
__device__ float g_h[2][Hn * Bn];                  // ping-pong hidden state (H, B)
__device__ int   g_rowptr[2][Hn + 1];              // [0]=hh, [1]=ih
__device__ int   g_cnt[2][Hn];
__device__ int   g_cur[2][Hn];
__device__ int   g_bsum[2][256];
__device__ int2  g_pairs[2][NNZn];                 // {col, float_as_int(val)}
__device__ int   g_wrow[2][MAXWARPS + 1];          // nnz-balanced warp->row ranges

// grid-barrier state for the persistent multistep kernel
__device__ unsigned int g_bar_count;               // monotonic arrivals
__device__ volatile unsigned int g_bar_phase;      // released step count

// ---------------- preprocessing -------------------------------------------

__global__ void init_kernel() {
    int i = blockIdx.x * blockDim.x + threadIdx.x;
    if (i < Hn * Bn) g_h[0][i] = 0.0f;
    if (i < Hn) { g_cnt[0][i] = 0; g_cnt[1][i] = 0; }
    if (i == 0) { g_bar_count = 0; g_bar_phase = 0; }
}

// fused histogram over both matrices (gridDim.y selects matrix)
__global__ void hist_kernel(const int* __restrict__ hh_idx,
                            const int* __restrict__ ih_idx) {
    int j = blockIdx.x * blockDim.x + threadIdx.x;
    int m = blockIdx.y;
    if (j >= NNZn) return;
    const int* rows = m ? ih_idx : hh_idx;
    atomicAdd(&g_cnt[m][rows[j]], 1);
}

// phase 1: per-block inclusive scan of 256 counts
__global__ void scan1_kernel() {
    int m = blockIdx.y;
    int i = blockIdx.x * 256 + threadIdx.x;
    int v = (i < Hn) ? g_cnt[m][i] : 0;
    int lane = threadIdx.x & 31, w = threadIdx.x >> 5;
    int x = v;
#pragma unroll
    for (int o = 1; o < 32; o <<= 1) {
        int y = __shfl_up_sync(~0u, x, o);
        if (lane >= o) x += y;
    }
    __shared__ int wsum[8];
    if (lane == 31) wsum[w] = x;
    __syncthreads();
    if (w == 0 && lane < 8) {
        int y = wsum[lane];
#pragma unroll
        for (int o = 1; o < 8; o <<= 1) {
            int z = __shfl_up_sync(0xffu, y, o);
            if (lane >= o) y += z;
        }
        wsum[lane] = y;
    }
    __syncthreads();
    int incl = x + (w > 0 ? wsum[w - 1] : 0);
    if (i < Hn) g_rowptr[m][i] = incl - v;          // local exclusive
    if (threadIdx.x == 255) g_bsum[m][blockIdx.x] = incl;
}

// phase 2: scan the (<=256) block sums
__global__ void scan2_kernel() {
    int m = blockIdx.y;
    int t = threadIdx.x;
    int v = (t < NB) ? g_bsum[m][t] : 0;
    int lane = t & 31, w = t >> 5;
    int x = v;
#pragma unroll
    for (int o = 1; o < 32; o <<= 1) {
        int y = __shfl_up_sync(~0u, x, o);
        if (lane >= o) x += y;
    }
    __shared__ int wsum[8];
    if (lane == 31) wsum[w] = x;
    __syncthreads();
    if (w == 0 && lane < 8) {
        int y = wsum[lane];
#pragma unroll
        for (int o = 1; o < 8; o <<= 1) {
            int z = __shfl_up_sync(0xffu, y, o);
            if (lane >= o) y += z;
        }
        wsum[lane] = y;
    }
    __syncthreads();
    int incl = x + (w > 0 ? wsum[w - 1] : 0);
    if (t < NB) g_bsum[m][t] = incl - v;
    if (t == 255) g_rowptr[m][Hn] = incl;           // total nnz
}

// phase 3: add block offsets; materialize rowptr + scatter cursor
__global__ void scan3_kernel() {
    int m = blockIdx.y;
    int i = blockIdx.x * 256 + threadIdx.x;
    if (i >= Hn) return;
    int r = g_rowptr[m][i] + g_bsum[m][blockIdx.x];
    g_rowptr[m][i] = r;
    g_cur[m][i]    = r;
}

// nnz-balanced partition: warp w of nwarps gets rows [wrow[w], wrow[w+1])
__global__ void partition_kernel(int m, int nwarps) {
    int w = blockIdx.x * blockDim.x + threadIdx.x;
    if (w > nwarps) return;
    if (w == nwarps) { g_wrow[m][w] = Hn; return; }
    int total = g_rowptr[m][Hn];
    long long target = (long long)w * total / nwarps;
    int lo = 0, hi = Hn;
    while (lo < hi) {                     // largest row with rowptr[row] <= target
        int mid = (lo + hi + 1) >> 1;
        if (g_rowptr[m][mid] <= (int)target) lo = mid; else hi = mid - 1;
    }
    g_wrow[m][w] = lo;
}

// fused scatter into CSR pair arrays (gridDim.y selects matrix)
__global__ void scatter_kernel(const int* __restrict__ hh_idx,
                               const float* __restrict__ hh_vals,
                               const int* __restrict__ ih_idx,
                               const float* __restrict__ ih_vals) {
    int j = blockIdx.x * blockDim.x + threadIdx.x;
    int m = blockIdx.y;
    if (j >= NNZn) return;
    const int*   idx  = m ? ih_idx  : hh_idx;
    const float* vals = m ? ih_vals : hh_vals;
    int r = idx[j];
    int c = idx[NNZn + j];
    int p = atomicAdd(&g_cur[m][r], 1);
    g_pairs[m][p] = make_int2(c, __float_as_int(vals[j]));
}

// x (B, T, IN) -> g_xT (T, IN, B)
__global__ void transpose_kernel(const float* __restrict__ x) {
    int idx = blockIdx.x * blockDim.x + threadIdx.x;   // over T*IN
    if (idx >= Tn * INn) return;
    int t = idx / INn;
    int c = idx - t * INn;
    float v[Bn];
#pragma unroll
    for (int b = 0; b < Bn; ++b)
        v[b] = x[(size_t)b * Tn * INn + (size_t)t * INn + c];
    float4* dst = reinterpret_cast<float4*>(&g_xT[(size_t)idx * Bn]);
    dst[0] = make_float4(v[0], v[1], v[2], v[3]);
    dst[1] = make_float4(v[4], v[5], v[6], v[7]);
}

// ---------------- main compute ---------------------------------------------

// ih_pre[t, r, b] = bias[r] + sum_j ih_val[j] * xT[t, col[j], b]
__global__ void __launch_bounds__(256) ih_kernel(const float* __restrict__ bias) {
    int w = blockIdx.x * 8 + (threadIdx.x >> 5);
    int sub = (threadIdx.x >> 3) & 3;
    int b   = threadIdx.x & 7;
    int rbeg = g_wrow[1][w];
    int rend = g_wrow[1][w + 1];
    for (int r0 = rbeg; r0 < rend; r0 += 4) {
        int g = r0 + sub;
        if (g >= rend) continue;
        float bv = bias[g];
        float acc[Tn];
#pragma unroll
        for (int t = 0; t < Tn; ++t) acc[t] = bv;
        int jb = g_rowptr[1][g];
        int je = g_rowptr[1][g + 1];
        for (int j = jb; j < je; ++j) {
            int2 p = g_pairs[1][j];
            float v = __int_as_float(p.y);
            const float* xp = g_xT + (size_t)p.x * Bn + b;
#pragma unroll
            for (int t = 0; t < Tn; ++t)
                acc[t] += v * xp[(size_t)t * INn * Bn];
        }
#pragma unroll
        for (int t = 0; t < Tn; ++t)
            g_ihpre[((size_t)t * Hn + g) * Bn + b] = acc[t];
    }
}

// persistent recurrence kernel. 512 threads = 16 warps per block.
// The block's CSR pairs are loaded into SMEM ONCE and reused for all 32 steps.
// h reads/writes via __ldcg/__stcg (L2 is the coherence point across barriers).
__global__ void __launch_bounds__(512)
multistep_kernel(const float* __restrict__ ihpre, float* __restrict__ out) {
    __shared__ int2 s_pairs[SPAIRS];

    const int wib = threadIdx.x >> 5;                 // warp in block
    const int w   = blockIdx.x * 16 + wib;            // global warp id
    const int sub = (threadIdx.x >> 3) & 3;           // row-within-chunk
    const int b   = threadIdx.x & 7;                  // batch lane
    const unsigned nblocks = gridDim.x;

    const int rbeg = g_wrow[0][w];
    const int rend = g_wrow[0][w + 1];
    const int blk_rbeg = g_wrow[0][blockIdx.x * 16];
    const int blk_rend = g_wrow[0][blockIdx.x * 16 + 16];
    const int base     = g_rowptr[0][blk_rbeg];
    const int nnz_blk  = g_rowptr[0][blk_rend] - base;
    const bool use_smem = (nnz_blk <= SPAIRS);

    if (use_smem) {
        for (int i = threadIdx.x; i < nnz_blk; i += 512)
            s_pairs[i] = g_pairs[0][base + i];
    }
    __syncthreads();

    for (int t = 0; t < Tn; ++t) {
        const float* hprev = g_h[t & 1];
        float*       hnext = g_h[(t + 1) & 1];
        const float* ihp   = ihpre + (size_t)t * Hn * Bn;
        float*       outt  = out + (size_t)t * Hn;
        const bool   last  = (t + 1 == Tn);

        for (int r0 = rbeg; r0 < rend; r0 += 4) {
            int g = r0 + sub;
            if (g < rend) {
                float acc = ihp[g * Bn + b];
                int jb = g_rowptr[0][g];
                int je = g_rowptr[0][g + 1];
                if (use_smem) {
#pragma unroll 4
                    for (int j = jb; j < je; ++j) {
                        int2 p = s_pairs[j - base];
                        acc += __int_as_float(p.y) * __ldcg(&hprev[p.x * Bn + b]);
                    }
                } else {
#pragma unroll 4
                    for (int j = jb; j < je; ++j) {
                        int2 p = g_pairs[0][j];
                        acc += __int_as_float(p.y) * __ldcg(&hprev[p.x * Bn + b]);
                    }
                }
                float hv = tanhf(acc);
                if (!last) __stcg(&hnext[g * Bn + b], hv);
                outt[(size_t)b * Tn * Hn + g] = hv;   // out layout (B, T, H)
            }
        }

        if (last) break;                  // no barrier after final step

        // ---- grid-wide barrier ----
        __threadfence();                  // release: h writes visible at L2
        __syncthreads();
        if (threadIdx.x == 0) {
            unsigned target = (unsigned)(t + 1);
            unsigned old = atomicAdd(&g_bar_count, 1u);
            if (old == nblocks * target - 1u) {
                g_bar_phase = target;                      // release step
            } else {
                while (g_bar_phase < target) { }           // tight volatile spin
            }
        }
        __syncthreads();
    }
}

// ---------------- launch ----------------------------------------------------

extern "C" void kernel_launch(void* const* d_in, const int* in_sizes, int n_in,
                              void* d_out, int out_size) {
    const float* x        = (const float*)d_in[0];   // (B, T, IN)
    const float* hh_vals  = (const float*)d_in[1];   // (NNZ,)
    const float* hh_bias  = (const float*)d_in[2];   // (H, 1)
    const float* ih_vals  = (const float*)d_in[3];   // (NNZ,)
    const int*   hh_idx   = (const int*)d_in[4];     // (2, NNZ): rows then cols
    const int*   ih_idx   = (const int*)d_in[5];     // (2, NNZ)
    float*       out      = (float*)d_out;           // (B, T, H)

    float* ihpre_p;
    cudaGetSymbolAddress((void**)&ihpre_p, g_ihpre);

    const int TPB = 256;

    // grid sizing: all blocks wave-1 resident (deadlock-free barrier)
    int sm_count = 0, occ_ms = 0, occ_ih = 0;
    cudaDeviceGetAttribute(&sm_count, cudaDevAttrMultiProcessorCount, 0);
    cudaOccupancyMaxActiveBlocksPerMultiprocessor(&occ_ms, multistep_kernel, 512, 0);
    cudaOccupancyMaxActiveBlocksPerMultiprocessor(&occ_ih, ih_kernel, 256, 0);
    if (sm_count <= 0) sm_count = 1;
    if (occ_ms <= 0) occ_ms = 1;
    if (occ_ih <= 0) occ_ih = 1;
    int grid_ms = sm_count * occ_ms; if (grid_ms > 1000) grid_ms = 1000;
    int grid_ih = sm_count * occ_ih; if (grid_ih > 2048) grid_ih = 2048;
    int nw_ms = grid_ms * 16;
    int nw_ih = grid_ih * 8;

    // 1) init counters + h0 + barrier state
    init_kernel<<<(Hn * Bn + TPB - 1) / TPB, TPB>>>();

    // 2) fused histograms
    dim3 hg((NNZn + TPB - 1) / TPB, 2);
    hist_kernel<<<hg, TPB>>>(hh_idx, ih_idx);

    // 3) hierarchical scans -> rowptr + cursor (both matrices at once)
    dim3 sg(NB, 2);
    scan1_kernel<<<sg, 256>>>();
    scan2_kernel<<<dim3(1, 2), 256>>>();
    scan3_kernel<<<sg, 256>>>();

    // 3b) nnz-balanced warp partitions
    partition_kernel<<<(nw_ms + TPB) / TPB, TPB>>>(0, nw_ms);
    partition_kernel<<<(nw_ih + TPB) / TPB, TPB>>>(1, nw_ih);

    // 4) fused scatter into CSR pair arrays
    scatter_kernel<<<hg, TPB>>>(hh_idx, hh_vals, ih_idx, ih_vals);

    // 5) transpose x -> (T, IN, B)
    transpose_kernel<<<(Tn * INn + TPB - 1) / TPB, TPB>>>(x);

    // 6) all 32 input-path spmms (+ bias folded in), nnz-balanced
    ih_kernel<<<grid_ih, 256>>>(hh_bias);

    // 7) persistent recurrence kernel with smem-cached pairs
    multistep_kernel<<<grid_ms, 512>>>(ihpre_p, out);
}

// round 6
// speedup vs baseline: 1.0893x; 1.0893x over previous
#include <cuda_runtime.h>

// Problem constants (from reference_code)
#define Hn    50000
#define INn   50000
#define NNZn  800000
#define Bn    8
#define Tn    32

#define NB        ((Hn + 255) / 256)   // 196 scan blocks per matrix
#define NWARPS    12544                // balanced warps (1568 blocks x 8 warps)
#define NBLOCKS   (NWARPS / 8)

// ---------------- device scratch (static globals; no runtime allocation) ----
__device__ float g_xT[(size_t)Tn * INn * Bn];      // x transposed -> (T, IN, B)
__device__ float g_ihpre[(size_t)Tn * Hn * Bn];    // ih spmm + bias, (T, H, B)
__device__ float g_h[2][Hn * Bn];                  // ping-pong hidden state (H, B)
__device__ int   g_rowptr[2][Hn + 1];              // [0]=hh, [1]=ih
__device__ int   g_cnt[2][Hn];
__device__ int   g_cur[2][Hn];
__device__ int   g_bsum[2][256];
__device__ int2  g_pairs[2][NNZn];                 // {col, float_as_int(val)}
__device__ int   g_wrow[2][NWARPS + 1];            // nnz-balanced warp->row ranges

// ---------------- preprocessing -------------------------------------------

__global__ void init_kernel() {
    int i = blockIdx.x * blockDim.x + threadIdx.x;
    if (i < Hn * Bn) g_h[0][i] = 0.0f;
    if (i < Hn) { g_cnt[0][i] = 0; g_cnt[1][i] = 0; }
}

// fused histogram over both matrices (gridDim.y selects matrix)
__global__ void hist_kernel(const int* __restrict__ hh_idx,
                            const int* __restrict__ ih_idx) {
    int j = blockIdx.x * blockDim.x + threadIdx.x;
    int m = blockIdx.y;
    if (j >= NNZn) return;
    const int* rows = m ? ih_idx : hh_idx;
    atomicAdd(&g_cnt[m][rows[j]], 1);
}

// phase 1: per-block inclusive scan of 256 counts
__global__ void scan1_kernel() {
    int m = blockIdx.y;
    int i = blockIdx.x * 256 + threadIdx.x;
    int v = (i < Hn) ? g_cnt[m][i] : 0;
    int lane = threadIdx.x & 31, w = threadIdx.x >> 5;
    int x = v;
#pragma unroll
    for (int o = 1; o < 32; o <<= 1) {
        int y = __shfl_up_sync(~0u, x, o);
        if (lane >= o) x += y;
    }
    __shared__ int wsum[8];
    if (lane == 31) wsum[w] = x;
    __syncthreads();
    if (w == 0 && lane < 8) {
        int y = wsum[lane];
#pragma unroll
        for (int o = 1; o < 8; o <<= 1) {
            int z = __shfl_up_sync(0xffu, y, o);
            if (lane >= o) y += z;
        }
        wsum[lane] = y;
    }
    __syncthreads();
    int incl = x + (w > 0 ? wsum[w - 1] : 0);
    if (i < Hn) g_rowptr[m][i] = incl - v;          // local exclusive
    if (threadIdx.x == 255) g_bsum[m][blockIdx.x] = incl;
}

// phase 2: scan the (<=256) block sums
__global__ void scan2_kernel() {
    int m = blockIdx.y;
    int t = threadIdx.x;
    int v = (t < NB) ? g_bsum[m][t] : 0;
    int lane = t & 31, w = t >> 5;
    int x = v;
#pragma unroll
    for (int o = 1; o < 32; o <<= 1) {
        int y = __shfl_up_sync(~0u, x, o);
        if (lane >= o) x += y;
    }
    __shared__ int wsum[8];
    if (lane == 31) wsum[w] = x;
    __syncthreads();
    if (w == 0 && lane < 8) {
        int y = wsum[lane];
#pragma unroll
        for (int o = 1; o < 8; o <<= 1) {
            int z = __shfl_up_sync(0xffu, y, o);
            if (lane >= o) y += z;
        }
        wsum[lane] = y;
    }
    __syncthreads();
    int incl = x + (w > 0 ? wsum[w - 1] : 0);
    if (t < NB) g_bsum[m][t] = incl - v;
    if (t == 255) g_rowptr[m][Hn] = incl;           // total nnz
}

// phase 3: add block offsets; materialize rowptr + scatter cursor
__global__ void scan3_kernel() {
    int m = blockIdx.y;
    int i = blockIdx.x * 256 + threadIdx.x;
    if (i >= Hn) return;
    int r = g_rowptr[m][i] + g_bsum[m][blockIdx.x];
    g_rowptr[m][i] = r;
    g_cur[m][i]    = r;
}

// nnz-balanced partition for both matrices (gridDim.y selects matrix):
// warp w gets rows [wrow[w], wrow[w+1]) holding ~total/NWARPS nonzeros.
__global__ void partition_kernel() {
    int w = blockIdx.x * blockDim.x + threadIdx.x;
    int m = blockIdx.y;
    if (w > NWARPS) return;
    if (w == NWARPS) { g_wrow[m][w] = Hn; return; }
    int total = g_rowptr[m][Hn];
    long long target = (long long)w * total / NWARPS;
    int lo = 0, hi = Hn;
    while (lo < hi) {                     // largest row with rowptr[row] <= target
        int mid = (lo + hi + 1) >> 1;
        if (g_rowptr[m][mid] <= (int)target) lo = mid; else hi = mid - 1;
    }
    g_wrow[m][w] = lo;
}

// fused scatter into CSR pair arrays (gridDim.y selects matrix)
__global__ void scatter_kernel(const int* __restrict__ hh_idx,
                               const float* __restrict__ hh_vals,
                               const int* __restrict__ ih_idx,
                               const float* __restrict__ ih_vals) {
    int j = blockIdx.x * blockDim.x + threadIdx.x;
    int m = blockIdx.y;
    if (j >= NNZn) return;
    const int*   idx  = m ? ih_idx  : hh_idx;
    const float* vals = m ? ih_vals : hh_vals;
    int r = idx[j];
    int c = idx[NNZn + j];
    int p = atomicAdd(&g_cur[m][r], 1);
    g_pairs[m][p] = make_int2(c, __float_as_int(vals[j]));
}

// x (B, T, IN) -> g_xT (T, IN, B)
__global__ void transpose_kernel(const float* __restrict__ x) {
    int idx = blockIdx.x * blockDim.x + threadIdx.x;   // over T*IN
    if (idx >= Tn * INn) return;
    int t = idx / INn;
    int c = idx - t * INn;
    float v[Bn];
#pragma unroll
    for (int b = 0; b < Bn; ++b)
        v[b] = x[(size_t)b * Tn * INn + (size_t)t * INn + c];
    float4* dst = reinterpret_cast<float4*>(&g_xT[(size_t)idx * Bn]);
    dst[0] = make_float4(v[0], v[1], v[2], v[3]);
    dst[1] = make_float4(v[4], v[5], v[6], v[7]);
}

// ---------------- main compute ---------------------------------------------

// ih_pre[t, r, b] = bias[r] + sum_j ih_val[j] * xT[t, col[j], b]
// warp processes its nnz-balanced row range; 4 rows in flight, 8 lanes = batch.
__global__ void __launch_bounds__(256) ih_kernel(const float* __restrict__ bias) {
    int w = blockIdx.x * 8 + (threadIdx.x >> 5);
    int sub = (threadIdx.x >> 3) & 3;
    int b   = threadIdx.x & 7;
    int rbeg = g_wrow[1][w];
    int rend = g_wrow[1][w + 1];
    for (int r0 = rbeg; r0 < rend; r0 += 4) {
        int g = r0 + sub;
        if (g >= rend) continue;
        float bv = __ldg(&bias[g]);
        float acc[Tn];
#pragma unroll
        for (int t = 0; t < Tn; ++t) acc[t] = bv;
        int jb = __ldg(&g_rowptr[1][g]);
        int je = __ldg(&g_rowptr[1][g + 1]);
        for (int j = jb; j < je; ++j) {
            int2 p = __ldg(&g_pairs[1][j]);
            float v = __int_as_float(p.y);
            const float* xp = g_xT + (size_t)p.x * Bn + b;
#pragma unroll
            for (int t = 0; t < Tn; ++t)
                acc[t] += v * xp[(size_t)t * INn * Bn];
        }
#pragma unroll
        for (int t = 0; t < Tn; ++t)
            g_ihpre[((size_t)t * Hn + g) * Bn + b] = acc[t];
    }
}

// one recurrence step, nnz-balanced: h_next = tanh(hh @ h_prev + ih_pre[t]).
// LAST templated so the dead hnext store disappears on the final step.
template <bool LAST>
__global__ void __launch_bounds__(256)
step_kernel(const float* __restrict__ hprev,
            float* __restrict__ hnext,
            const float* __restrict__ ihpre_t,
            float* __restrict__ out_t) {   // d_out + t*H
    int w   = blockIdx.x * 8 + (threadIdx.x >> 5);
    int sub = (threadIdx.x >> 3) & 3;     // row-within-chunk
    int b   = threadIdx.x & 7;            // batch lane
    int rbeg = g_wrow[0][w];
    int rend = g_wrow[0][w + 1];
    for (int r0 = rbeg; r0 < rend; r0 += 4) {
        int g = r0 + sub;
        if (g >= rend) continue;
        float acc = ihpre_t[g * Bn + b];
        int jb = __ldg(&g_rowptr[0][g]);
        int je = __ldg(&g_rowptr[0][g + 1]);
#pragma unroll 4
        for (int j = jb; j < je; ++j) {
            int2 p = __ldg(&g_pairs[0][j]);
            acc += __int_as_float(p.y) * hprev[p.x * Bn + b];
        }
        float hv = tanhf(acc);
        if (!LAST) hnext[g * Bn + b] = hv;
        out_t[(size_t)b * Tn * Hn + g] = hv;   // out layout (B, T, H)
    }
}

// ---------------- launch ----------------------------------------------------

extern "C" void kernel_launch(void* const* d_in, const int* in_sizes, int n_in,
                              void* d_out, int out_size) {
    const float* x        = (const float*)d_in[0];   // (B, T, IN)
    const float* hh_vals  = (const float*)d_in[1];   // (NNZ,)
    const float* hh_bias  = (const float*)d_in[2];   // (H, 1)
    const float* ih_vals  = (const float*)d_in[3];   // (NNZ,)
    const int*   hh_idx   = (const int*)d_in[4];     // (2, NNZ): rows then cols
    const int*   ih_idx   = (const int*)d_in[5];     // (2, NNZ)
    float*       out      = (float*)d_out;           // (B, T, H)

    float *ihpre_p, *h_p;
    cudaGetSymbolAddress((void**)&ihpre_p, g_ihpre);
    cudaGetSymbolAddress((void**)&h_p,     g_h);

    const int TPB = 256;

    // 1) init counters + h0
    init_kernel<<<(Hn * Bn + TPB - 1) / TPB, TPB>>>();

    // 2) fused histograms
    dim3 hg((NNZn + TPB - 1) / TPB, 2);
    hist_kernel<<<hg, TPB>>>(hh_idx, ih_idx);

    // 3) hierarchical scans -> rowptr + cursor (both matrices at once)
    dim3 sg(NB, 2);
    scan1_kernel<<<sg, 256>>>();
    scan2_kernel<<<dim3(1, 2), 256>>>();
    scan3_kernel<<<sg, 256>>>();

    // 3b) nnz-balanced warp partitions, both matrices in one launch
    partition_kernel<<<dim3((NWARPS + TPB) / TPB, 2), TPB>>>();

    // 4) fused scatter into CSR pair arrays
    scatter_kernel<<<hg, TPB>>>(hh_idx, hh_vals, ih_idx, ih_vals);

    // 5) transpose x -> (T, IN, B)
    transpose_kernel<<<(Tn * INn + TPB - 1) / TPB, TPB>>>(x);

    // 6) all 32 input-path spmms (+ bias folded in), nnz-balanced
    ih_kernel<<<NBLOCKS, 256>>>(hh_bias);

    // 7) sequential recurrence: 32 nnz-balanced fused spmm+tanh steps
    for (int t = 0; t < Tn; ++t) {
        const float* hprev = h_p + (size_t)(t & 1) * Hn * Bn;
        float*       hnext = h_p + (size_t)((t + 1) & 1) * Hn * Bn;
        const float* ihp   = ihpre_p + (size_t)t * Hn * Bn;
        float*       outt  = out + (size_t)t * Hn;
        if (t + 1 < Tn)
            step_kernel<false><<<NBLOCKS, 256>>>(hprev, hnext, ihp, outt);
        else
            step_kernel<true><<<NBLOCKS, 256>>>(hprev, hnext, ihp, outt);
    }
}